// round 16
// baseline (speedup 1.0000x reference)
#include <cuda_runtime.h>
#include <cuda_fp16.h>
#include <cstdint>
#include <math.h>

#define CIN   256
#define COUT  128
#define M_DIM 16384
#define N_DIM 512
#define K_SP  2048               // spline K (orig space, even/odd permuted)
#define K_B   256                // silu K
#define NIT_SP 32                // sparse iters (64 orig k each)
#define NITER  36                // + 4 dense silu iters (64 k each)
#define NSTAGE 2

#define A_STRIDE 272
#define A_BYTES  (64 * A_STRIDE)
#define B_STRIDE 144
#define B_BYTES  (128 * B_STRIDE)
#define STAGE_BYTES (A_BYTES + B_BYTES)   // 35840
#define SMEM_BYTES (NSTAGE * STAGE_BYTES) // 71680

// ---------------- device scratch ----------------
__device__ __align__(256) __half g_Fs[(size_t)K_B * M_DIM];          // silu [c][m]
__device__ __align__(256) __half g_Fc[(size_t)(K_SP / 2) * M_DIM];   // compressed splines [k'][m]
__device__ __align__(256) __half g_Wsp[(size_t)N_DIM * K_SP];        // spline weights [n][k]
__device__ __align__(256) __half g_Wb[(size_t)N_DIM * K_B];          // silu weights [n][c]
// metadata, flat: [cp][m], entry m: lo16 = E(m), hi16 = E(m+8)  (valid for m%16<8)
__device__ __align__(256) uint32_t g_E32[(size_t)128 * M_DIM];
__device__ float g_Z[N_DIM];

// per-cell compression LUT: low16 = even parity, high16 = odd parity
// code = id0 | id1<<2 | src0<<4 | src1<<7   (src 7 => zero)
__constant__ uint32_t c_lut[12] = {
    948u  | (1012u << 16),   // j=0
    932u  | (948u  << 16),   // j=1
    404u  | (932u  << 16),   // j=2
    260u  | (404u  << 16),   // j=3
    409u  | (260u  << 16),   // j=4
    265u  | (409u  << 16),   // j=5
    414u  | (265u  << 16),   // j=6
    270u  | (414u  << 16),   // j=7
    252u  | (270u  << 16),   // j=8
    124u  | (252u  << 16),   // j=9
    1012u | (124u  << 16),   // j=10
    1012u | (1012u << 16),   // out of range
};

// ---------------- PTX helpers ----------------
__device__ __forceinline__ uint32_t smem_u32(const void* p) {
    uint32_t a;
    asm("{ .reg .u64 t; cvta.to.shared.u64 t, %1; cvt.u32.u64 %0, t; }" : "=r"(a) : "l"(p));
    return a;
}
__device__ __forceinline__ void cp_async16(uint32_t saddr, const void* gaddr) {
    asm volatile("cp.async.cg.shared.global [%0], [%1], 16;" :: "r"(saddr), "l"(gaddr) : "memory");
}
__device__ __forceinline__ void cp_commit() {
    asm volatile("cp.async.commit_group;" ::: "memory");
}
template <int N>
__device__ __forceinline__ void cp_wait() {
    asm volatile("cp.async.wait_group %0;" :: "n"(N) : "memory");
}
__device__ __forceinline__ void ldsm_x4(uint32_t a, uint32_t* r) {
    asm volatile("ldmatrix.sync.aligned.m8n8.x4.shared.b16 {%0,%1,%2,%3}, [%4];"
        : "=r"(r[0]), "=r"(r[1]), "=r"(r[2]), "=r"(r[3]) : "r"(a));
}
__device__ __forceinline__ void ldsm_x4_t(uint32_t a, uint32_t* r) {
    asm volatile("ldmatrix.sync.aligned.m8n8.x4.trans.shared.b16 {%0,%1,%2,%3}, [%4];"
        : "=r"(r[0]), "=r"(r[1]), "=r"(r[2]), "=r"(r[3]) : "r"(a));
}
__device__ __forceinline__ void mma16816(float* c, const uint32_t* a, uint32_t b0, uint32_t b1) {
    asm volatile("mma.sync.aligned.m16n8k16.row.col.f32.f16.f16.f32 "
        "{%0,%1,%2,%3}, {%4,%5,%6,%7}, {%8,%9}, {%0,%1,%2,%3};"
        : "+f"(c[0]), "+f"(c[1]), "+f"(c[2]), "+f"(c[3])
        : "r"(a[0]), "r"(a[1]), "r"(a[2]), "r"(a[3]), "r"(b0), "r"(b1));
}
__device__ __forceinline__ void mmasp(float* c, const uint32_t* a,
                                      uint32_t b0, uint32_t b1, uint32_t b2, uint32_t b3,
                                      uint32_t e) {
    asm volatile("mma.sp::ordered_metadata.sync.aligned.m16n8k32.row.col.f32.f16.f16.f32 "
        "{%0,%1,%2,%3}, {%4,%5,%6,%7}, {%8,%9,%10,%11}, {%0,%1,%2,%3}, %12, 0x0;"
        : "+f"(c[0]), "+f"(c[1]), "+f"(c[2]), "+f"(c[3])
        : "r"(a[0]), "r"(a[1]), "r"(a[2]), "r"(a[3]),
          "r"(b0), "r"(b1), "r"(b2), "r"(b3), "r"(e));
}

__device__ __forceinline__ float pick4(float w0, float w1, float w2, float w3, int s) {
    float r = 0.0f;
    r = (s == 0) ? w0 : r;
    r = (s == 1) ? w1 : r;
    r = (s == 2) ? w2 : r;
    r = (s == 3) ? w3 : r;
    return r;
}

// ---------------- exact Cox-de Boor (for b0 in wz) ----------------
__device__ __forceinline__ void bspline8(float x, float* outb) {
    float t[12];
#pragma unroll
    for (int i = 0; i < 12; i++) t[i] = (float)(i - 3) * 0.4f - 1.0f;
    float b[11];
#pragma unroll
    for (int j = 0; j < 11; j++) b[j] = (x >= t[j] && x < t[j + 1]) ? 1.0f : 0.0f;
#pragma unroll
    for (int k = 1; k <= 3; k++) {
#pragma unroll
        for (int j = 0; j + k < 11; j++) {
            float left  = (x - t[j]) / (t[j + k] - t[j]) * b[j];
            float right = (t[j + k + 1] - x) / (t[j + k + 1] - t[j + 1]) * b[j + 1];
            b[j] = left + right;
        }
    }
#pragma unroll
    for (int g = 0; g < 8; g++) outb[g] = b[g];
}

// feature compute for one x value: silu + 4 compressed spline vals + 8-bit meta
__device__ __forceinline__ void feat1(float xv, float* silu, float* v, uint32_t* byteE) {
    *silu = xv * __frcp_rn(1.0f + __expf(-xv));
    float s = (xv + 2.2f) * 2.5f;
    int j = (int)floorf(s);
    float u  = s - (float)j;
    float u2 = u * u, u3 = u2 * u, om = 1.0f - u;
    float w0 = om * om * om * (1.0f / 6.0f);
    float w1 = (3.0f * u3 - 6.0f * u2 + 4.0f) * (1.0f / 6.0f);
    float w2 = (-3.0f * u3 + 3.0f * u2 + 3.0f * u + 1.0f) * (1.0f / 6.0f);
    float w3 = u3 * (1.0f / 6.0f);
    int jj = (j >= 0 && j <= 10) ? j : 11;
    uint32_t code2 = c_lut[jj];
    uint32_t bE = 0;
#pragma unroll
    for (int par = 0; par < 2; par++) {
        uint32_t cd = (code2 >> (par * 16)) & 0xFFFFu;
        v[par * 2 + 0] = pick4(w0, w1, w2, w3, (int)((cd >> 4) & 7u));
        v[par * 2 + 1] = pick4(w0, w1, w2, w3, (int)((cd >> 7) & 7u));
        bE |= (cd & 15u) << (par * 4);
    }
    *byteE = bE;
}

__device__ __forceinline__ uint32_t pack_h2(float a, float b) {
    __half2 h = __floats2half2_rn(a, b);
    return *(uint32_t*)&h;
}

// ---------------- fused prep ----------------
// blocks [0, 4096): features per (c-pair, 512-m group). blocks [4096, 4224): weights+Z per o.
__global__ void k_prep(const float* __restrict__ x,
                       const float* __restrict__ base_w,
                       const float* __restrict__ spline_w) {
    __shared__ float red[4][256];
    __shared__ unsigned char shB[2][512];
    int bid = blockIdx.x;
    int tid = threadIdx.x;

    if (bid < 4096) {
        int cp    = bid >> 5;               // c-pair 0..127
        int mbase = (bid & 31) * 512;
        int half  = tid >> 7;               // channel within pair
        int mp    = tid & 127;
        int m     = mbase + mp * 4;         // 4 consecutive m, same batch row
        int c     = cp * 2 + half;
        int b     = m >> 10, hw = m & 1023;

        float4 xv = *(const float4*)(x + (((size_t)(b * CIN + c)) << 10) + hw);
        float s[4], v[4][4];
        uint32_t e[4];
        feat1(xv.x, &s[0], v[0], &e[0]);
        feat1(xv.y, &s[1], v[1], &e[1]);
        feat1(xv.z, &s[2], v[2], &e[2]);
        feat1(xv.w, &s[3], v[3], &e[3]);

        {
            uint2 p = { pack_h2(s[0], s[1]), pack_h2(s[2], s[3]) };
            *(uint2*)(g_Fs + (size_t)c * M_DIM + m) = p;
        }
#pragma unroll
        for (int sl = 0; sl < 4; sl++) {
            uint2 p = { pack_h2(v[0][sl], v[1][sl]), pack_h2(v[2][sl], v[3][sl]) };
            *(uint2*)(g_Fc + (size_t)(c * 4 + sl) * M_DIM + m) = p;
        }
#pragma unroll
        for (int i = 0; i < 4; i++)
            shB[half][mp * 4 + i] = (unsigned char)e[i];
        __syncthreads();

        // 256 valid metadata entries (ml % 16 < 8) for 512 m
        int ml = (tid >> 3) * 16 + (tid & 7);
        uint32_t lo = (uint32_t)shB[0][ml]     | ((uint32_t)shB[1][ml] << 8);
        uint32_t hi = (uint32_t)shB[0][ml + 8] | ((uint32_t)shB[1][ml + 8] << 8);
        g_E32[(size_t)cp * M_DIM + mbase + ml] = lo | (hi << 16);
        return;
    }

    // ------- weights + Z: one block per output channel o -------
    int o = bid - 4096;
    int c = tid;
    float b0[8];
    bspline8(0.0f, b0);
    const float* swo = spline_w + ((size_t)(o * CIN + c)) * 32;
    float zt[4];
#pragma unroll
    for (int mn = 0; mn < 4; mn++) {        // raw storage tap (fm, fn)
        float v[8];
        *(float4*)(v)     = *(const float4*)(swo + mn * 8);
        *(float4*)(v + 4) = *(const float4*)(swo + mn * 8 + 4);
        float z = 0.0f;
#pragma unroll
        for (int g = 0; g < 8; g++) z += b0[g] * v[g];
        zt[mn] = z;
        int n = o * 4 + (1 - (mn >> 1)) * 2 + (1 - (mn & 1));
        g_Wb[(size_t)n * K_B + c] =
            __float2half(base_w[((o * CIN + c) * 2 + (mn >> 1)) * 2 + (mn & 1)]);
        __half* dst = g_Wsp + (size_t)n * K_SP + c * 8;
#pragma unroll
        for (int p = 0; p < 8; p++) {
            int g = (p < 4) ? (2 * p) : (2 * (p - 4) + 1);   // even/odd permutation
            dst[p] = __float2half(v[g]);
        }
    }
#pragma unroll
    for (int mn = 0; mn < 4; mn++) red[mn][c] = zt[mn];
    __syncthreads();
    for (int s = 128; s > 0; s >>= 1) {
        if (c < s) {
#pragma unroll
            for (int mn = 0; mn < 4; mn++) red[mn][c] += red[mn][c + s];
        }
        __syncthreads();
    }
    if (c < 4) {
        float total = red[0][0] + red[1][0] + red[2][0] + red[3][0];
        int f = (1 - (c >> 1)) * 2 + (1 - (c & 1));
        g_Z[o * 4 + c] = total - red[f][0];
    }
}

// ---------------- stage loader ----------------
__device__ __forceinline__ void issue_loads(int it, int m0, int n0, int tid, uint32_t sb) {
    uint32_t stage = sb + (it & 1) * STAGE_BYTES;
    if (it < NIT_SP) {
#pragma unroll
        for (int t = 0; t < 6; t++) {
            int idx = tid + t * 256;
            const __half* src;
            uint32_t soff;
            if (idx < 512) {
                int r = idx >> 4, ch = idx & 15;
                src  = g_Fc + (size_t)(it * 32 + r) * M_DIM + m0 + ch * 8;
                soff = stage + r * A_STRIDE + ch * 16;
            } else {
                int i2 = idx - 512;
                int r = i2 >> 3, ch = i2 & 7;
                src  = g_Wsp + (size_t)(n0 + r) * K_SP + it * 64 + ch * 8;
                soff = stage + A_BYTES + r * B_STRIDE + ch * 16;
            }
            cp_async16(soff, src);
        }
    } else {
        int i3 = it - NIT_SP;
#pragma unroll
        for (int t = 0; t < 8; t++) {
            int idx = tid + t * 256;
            const __half* src;
            uint32_t soff;
            if (idx < 1024) {
                int r = idx >> 4, ch = idx & 15;
                src  = g_Fs + (size_t)(i3 * 64 + r) * M_DIM + m0 + ch * 8;
                soff = stage + r * A_STRIDE + ch * 16;
            } else {
                int i2 = idx - 1024;
                int r = i2 >> 3, ch = i2 & 7;
                src  = g_Wb + (size_t)(n0 + r) * K_B + i3 * 64 + ch * 8;
                soff = stage + A_BYTES + r * B_STRIDE + ch * 16;
            }
            cp_async16(soff, src);
        }
    }
}

// ---------------- GEMM: sparse spline + dense silu, fp16, +Z epilogue ----------------
__global__ void __launch_bounds__(256, 2) k_gemm(float* __restrict__ out) {
    extern __shared__ char smem[];
    uint32_t sb = smem_u32(smem);
    const int tid  = threadIdx.x;
    const int wid  = tid >> 5, lane = tid & 31;
    const int wm   = wid >> 2;           // 0..1 (m: 64 each)
    const int wn   = wid & 3;            // 0..3 (n: 32 each)
    const int m0   = blockIdx.y * 128;
    const int n0   = blockIdx.x * 128;
    const int grp  = lane >> 3, lr = lane & 7;

    const uint32_t a_off = (uint32_t)(((grp >> 1) * 8 + lr) * A_STRIDE +
                                      (grp & 1) * 16 + wm * 128);
    const uint32_t b_off = (uint32_t)(((grp & 1) * 8 + lr) * B_STRIDE +
                                      (grp >> 1) * 16 + wn * 32 * B_STRIDE);

    float acc[4][4][4];
#pragma unroll
    for (int i = 0; i < 4; i++)
#pragma unroll
        for (int j = 0; j < 4; j++)
#pragma unroll
            for (int v = 0; v < 4; v++) acc[i][j][v] = 0.0f;

    issue_loads(0, m0, n0, tid, sb); cp_commit();
    issue_loads(1, m0, n0, tid, sb); cp_commit();

    const int erow = wm * 64 + (lane >> 2);   // frag-relative metadata row
    const int ekh  = lane & 1;                 // metadata k-half
    // per-thread metadata base: row index part is iteration-invariant
    const uint32_t* __restrict__ ebase =
        g_E32 + (size_t)ekh * M_DIM + m0 + erow;

    for (int it = 0; it < NITER; it++) {
        // issue metadata LDGs BEFORE the pipeline wait/barrier so their latency
        // overlaps the cp.async wait (ptxas won't hoist LDG across BAR itself)
        uint32_t E[2][4];
        if (it < NIT_SP) {
#pragma unroll
            for (int q = 0; q < 2; q++) {
                size_t cpoff = (size_t)((it * 2 + q) * 2) * M_DIM;
#pragma unroll
                for (int mf = 0; mf < 4; mf++)
                    E[q][mf] = __ldg(ebase + cpoff + mf * 16);
            }
        }

        cp_wait<1>();
        __syncthreads();
        uint32_t st = sb + (it & 1) * STAGE_BYTES;

        if (it < NIT_SP) {
#pragma unroll
            for (int q = 0; q < 2; q++) {
                uint32_t ac[4][4];
                uint32_t a_base = st + q * (16 * A_STRIDE) + a_off;
#pragma unroll
                for (int mf = 0; mf < 4; mf++)
                    ldsm_x4_t(a_base + mf * 32, ac[mf]);

                uint32_t bb = st + A_BYTES + q * 64 + b_off;
                uint32_t bA[2][4], bB[2][4];
#pragma unroll
                for (int u = 0; u < 2; u++) {
                    ldsm_x4(bb + u * (16 * B_STRIDE), bA[u]);
                    ldsm_x4(bb + 32 + u * (16 * B_STRIDE), bB[u]);
                }
#pragma unroll
                for (int mf = 0; mf < 4; mf++) {
#pragma unroll
                    for (int nf = 0; nf < 4; nf++) {
                        int u = nf >> 1, h = nf & 1;
                        mmasp(acc[mf][nf], ac[mf],
                              bA[u][h], bA[u][h + 2], bB[u][h], bB[u][h + 2],
                              E[q][mf]);
                    }
                }
            }
        } else {
#pragma unroll
            for (int kk = 0; kk < 4; kk++) {
                uint32_t ah[4][4], bh[2][4];
                uint32_t a_base = st + kk * (16 * A_STRIDE) + a_off;
                uint32_t b_base = st + A_BYTES + kk * 32 + b_off;
#pragma unroll
                for (int mf = 0; mf < 4; mf++)
                    ldsm_x4_t(a_base + mf * 32, ah[mf]);
#pragma unroll
                for (int u = 0; u < 2; u++)
                    ldsm_x4(b_base + u * (16 * B_STRIDE), bh[u]);
#pragma unroll
                for (int mf = 0; mf < 4; mf++) {
#pragma unroll
                    for (int nf = 0; nf < 4; nf++) {
                        int u = nf >> 1, h = nf & 1;
                        mma16816(acc[mf][nf], ah[mf], bh[u][h], bh[u][h + 2]);
                    }
                }
            }
        }
        __syncthreads();
        int lt = it + NSTAGE;
        if (lt < NITER) issue_loads(lt, m0, n0, tid, sb);
        cp_commit();
    }

    // ---------------- epilogue: add Z, scatter to ConvTranspose layout ----------------
#pragma unroll
    for (int nf = 0; nf < 4; nf++) {
        int n  = n0 + wn * 32 + nf * 8 + (lane & 3) * 2;
        int o  = n >> 2, mi = (n >> 1) & 1;
        float z0 = __ldg(&g_Z[n]), z1 = __ldg(&g_Z[n + 1]);
#pragma unroll
        for (int mf = 0; mf < 4; mf++) {
#pragma unroll
            for (int half = 0; half < 2; half++) {
                int m = m0 + wm * 64 + mf * 16 + (lane >> 2) + half * 8;
                int b = m >> 10, h = (m >> 5) & 31, w = m & 31;
                float2 v;
                v.x = acc[mf][nf][half * 2 + 0] + z0;
                v.y = acc[mf][nf][half * 2 + 1] + z1;
                *(float2*)(out + ((size_t)((b * COUT + o) * 64 + 2 * h + mi)) * 64 + 2 * w) = v;
            }
        }
    }
}

extern "C" void kernel_launch(void* const* d_in, const int* in_sizes, int n_in,
                              void* d_out, int out_size) {
    const float* x        = (const float*)d_in[0];
    const float* base_w   = (const float*)d_in[1];
    const float* spline_w = (const float*)d_in[2];
    float* out = (float*)d_out;

    cudaFuncSetAttribute(k_gemm, cudaFuncAttributeMaxDynamicSharedMemorySize, SMEM_BYTES);

    k_prep<<<4096 + COUT, 256>>>(x, base_w, spline_w);
    dim3 grid(N_DIM / 128, M_DIM / 128);     // (4, 128) = 512 CTAs
    k_gemm<<<grid, 256, SMEM_BYTES>>>(out);
}

// round 17
// speedup vs baseline: 1.1410x; 1.1410x over previous
#include <cuda_runtime.h>
#include <cuda_fp16.h>
#include <cstdint>
#include <math.h>

#define CIN   256
#define COUT  128
#define M_DIM 16384
#define N_DIM 512
#define K_SP  2048               // spline K (orig space, even/odd permuted)
#define K_B   256                // silu K
#define NIT_SP 32                // sparse iters (64 orig k each)
#define NITER  36                // + 4 dense silu iters (64 k each)
#define NSTAGE 3

#define A_STRIDE 272
#define A_BYTES  (64 * A_STRIDE)
#define B_STRIDE 144
#define B_BYTES  (128 * B_STRIDE)
#define STAGE_BYTES (A_BYTES + B_BYTES)   // 35840
#define SMEM_BYTES (NSTAGE * STAGE_BYTES) // 107520 -> still 2 CTAs/SM

// ---------------- device scratch ----------------
__device__ __align__(256) __half g_Fs[(size_t)K_B * M_DIM];          // silu [c][m]
__device__ __align__(256) __half g_Fc[(size_t)(K_SP / 2) * M_DIM];   // compressed splines [k'][m]
__device__ __align__(256) __half g_Wsp[(size_t)N_DIM * K_SP];        // spline weights [n][k]
__device__ __align__(256) __half g_Wb[(size_t)N_DIM * K_B];          // silu weights [n][c]
// metadata, flat: [cp][m], entry m: lo16 = E(m), hi16 = E(m+8)  (valid for m%16<8)
__device__ __align__(256) uint32_t g_E32[(size_t)128 * M_DIM];
__device__ float g_Z[N_DIM];

// per-cell compression LUT: low16 = even parity, high16 = odd parity
// code = id0 | id1<<2 | src0<<4 | src1<<7   (src 7 => zero)
__constant__ uint32_t c_lut[12] = {
    948u  | (1012u << 16),   // j=0
    932u  | (948u  << 16),   // j=1
    404u  | (932u  << 16),   // j=2
    260u  | (404u  << 16),   // j=3
    409u  | (260u  << 16),   // j=4
    265u  | (409u  << 16),   // j=5
    414u  | (265u  << 16),   // j=6
    270u  | (414u  << 16),   // j=7
    252u  | (270u  << 16),   // j=8
    124u  | (252u  << 16),   // j=9
    1012u | (124u  << 16),   // j=10
    1012u | (1012u << 16),   // out of range
};

// ---------------- PTX helpers ----------------
__device__ __forceinline__ uint32_t smem_u32(const void* p) {
    uint32_t a;
    asm("{ .reg .u64 t; cvta.to.shared.u64 t, %1; cvt.u32.u64 %0, t; }" : "=r"(a) : "l"(p));
    return a;
}
__device__ __forceinline__ void cp_async16(uint32_t saddr, const void* gaddr) {
    asm volatile("cp.async.cg.shared.global [%0], [%1], 16;" :: "r"(saddr), "l"(gaddr) : "memory");
}
__device__ __forceinline__ void cp_commit() {
    asm volatile("cp.async.commit_group;" ::: "memory");
}
template <int N>
__device__ __forceinline__ void cp_wait() {
    asm volatile("cp.async.wait_group %0;" :: "n"(N) : "memory");
}
__device__ __forceinline__ void ldsm_x4(uint32_t a, uint32_t* r) {
    asm volatile("ldmatrix.sync.aligned.m8n8.x4.shared.b16 {%0,%1,%2,%3}, [%4];"
        : "=r"(r[0]), "=r"(r[1]), "=r"(r[2]), "=r"(r[3]) : "r"(a));
}
__device__ __forceinline__ void ldsm_x4_t(uint32_t a, uint32_t* r) {
    asm volatile("ldmatrix.sync.aligned.m8n8.x4.trans.shared.b16 {%0,%1,%2,%3}, [%4];"
        : "=r"(r[0]), "=r"(r[1]), "=r"(r[2]), "=r"(r[3]) : "r"(a));
}
__device__ __forceinline__ void mma16816(float* c, const uint32_t* a, uint32_t b0, uint32_t b1) {
    asm volatile("mma.sync.aligned.m16n8k16.row.col.f32.f16.f16.f32 "
        "{%0,%1,%2,%3}, {%4,%5,%6,%7}, {%8,%9}, {%0,%1,%2,%3};"
        : "+f"(c[0]), "+f"(c[1]), "+f"(c[2]), "+f"(c[3])
        : "r"(a[0]), "r"(a[1]), "r"(a[2]), "r"(a[3]), "r"(b0), "r"(b1));
}
__device__ __forceinline__ void mmasp(float* c, const uint32_t* a,
                                      uint32_t b0, uint32_t b1, uint32_t b2, uint32_t b3,
                                      uint32_t e) {
    asm volatile("mma.sp::ordered_metadata.sync.aligned.m16n8k32.row.col.f32.f16.f16.f32 "
        "{%0,%1,%2,%3}, {%4,%5,%6,%7}, {%8,%9,%10,%11}, {%0,%1,%2,%3}, %12, 0x0;"
        : "+f"(c[0]), "+f"(c[1]), "+f"(c[2]), "+f"(c[3])
        : "r"(a[0]), "r"(a[1]), "r"(a[2]), "r"(a[3]),
          "r"(b0), "r"(b1), "r"(b2), "r"(b3), "r"(e));
}

__device__ __forceinline__ float pick4(float w0, float w1, float w2, float w3, int s) {
    float r = 0.0f;
    r = (s == 0) ? w0 : r;
    r = (s == 1) ? w1 : r;
    r = (s == 2) ? w2 : r;
    r = (s == 3) ? w3 : r;
    return r;
}

// ---------------- exact Cox-de Boor (for b0 in wz) ----------------
__device__ __forceinline__ void bspline8(float x, float* outb) {
    float t[12];
#pragma unroll
    for (int i = 0; i < 12; i++) t[i] = (float)(i - 3) * 0.4f - 1.0f;
    float b[11];
#pragma unroll
    for (int j = 0; j < 11; j++) b[j] = (x >= t[j] && x < t[j + 1]) ? 1.0f : 0.0f;
#pragma unroll
    for (int k = 1; k <= 3; k++) {
#pragma unroll
        for (int j = 0; j + k < 11; j++) {
            float left  = (x - t[j]) / (t[j + k] - t[j]) * b[j];
            float right = (t[j + k + 1] - x) / (t[j + k + 1] - t[j + 1]) * b[j + 1];
            b[j] = left + right;
        }
    }
#pragma unroll
    for (int g = 0; g < 8; g++) outb[g] = b[g];
}

// feature compute for one x value: silu + 4 compressed spline vals + 8-bit meta
__device__ __forceinline__ void feat1(float xv, float* silu, float* v, uint32_t* byteE) {
    *silu = xv * __frcp_rn(1.0f + __expf(-xv));
    float s = (xv + 2.2f) * 2.5f;
    int j = (int)floorf(s);
    float u  = s - (float)j;
    float u2 = u * u, u3 = u2 * u, om = 1.0f - u;
    float w0 = om * om * om * (1.0f / 6.0f);
    float w1 = (3.0f * u3 - 6.0f * u2 + 4.0f) * (1.0f / 6.0f);
    float w2 = (-3.0f * u3 + 3.0f * u2 + 3.0f * u + 1.0f) * (1.0f / 6.0f);
    float w3 = u3 * (1.0f / 6.0f);
    int jj = (j >= 0 && j <= 10) ? j : 11;
    uint32_t code2 = c_lut[jj];
    uint32_t bE = 0;
#pragma unroll
    for (int par = 0; par < 2; par++) {
        uint32_t cd = (code2 >> (par * 16)) & 0xFFFFu;
        v[par * 2 + 0] = pick4(w0, w1, w2, w3, (int)((cd >> 4) & 7u));
        v[par * 2 + 1] = pick4(w0, w1, w2, w3, (int)((cd >> 7) & 7u));
        bE |= (cd & 15u) << (par * 4);
    }
    *byteE = bE;
}

__device__ __forceinline__ uint32_t pack_h2(float a, float b) {
    __half2 h = __floats2half2_rn(a, b);
    return *(uint32_t*)&h;
}

// ---------------- fused prep ----------------
// blocks [0, 4096): features per (c-pair, 512-m group). blocks [4096, 4224): weights+Z per o.
__global__ void k_prep(const float* __restrict__ x,
                       const float* __restrict__ base_w,
                       const float* __restrict__ spline_w) {
    __shared__ float red[4][256];
    __shared__ unsigned char shB[2][512];
    int bid = blockIdx.x;
    int tid = threadIdx.x;

    if (bid < 4096) {
        int cp    = bid >> 5;               // c-pair 0..127
        int mbase = (bid & 31) * 512;
        int half  = tid >> 7;               // channel within pair
        int mp    = tid & 127;
        int m     = mbase + mp * 4;         // 4 consecutive m, same batch row
        int c     = cp * 2 + half;
        int b     = m >> 10, hw = m & 1023;

        float4 xv = *(const float4*)(x + (((size_t)(b * CIN + c)) << 10) + hw);
        float s[4], v[4][4];
        uint32_t e[4];
        feat1(xv.x, &s[0], v[0], &e[0]);
        feat1(xv.y, &s[1], v[1], &e[1]);
        feat1(xv.z, &s[2], v[2], &e[2]);
        feat1(xv.w, &s[3], v[3], &e[3]);

        {
            uint2 p = { pack_h2(s[0], s[1]), pack_h2(s[2], s[3]) };
            *(uint2*)(g_Fs + (size_t)c * M_DIM + m) = p;
        }
#pragma unroll
        for (int sl = 0; sl < 4; sl++) {
            uint2 p = { pack_h2(v[0][sl], v[1][sl]), pack_h2(v[2][sl], v[3][sl]) };
            *(uint2*)(g_Fc + (size_t)(c * 4 + sl) * M_DIM + m) = p;
        }
#pragma unroll
        for (int i = 0; i < 4; i++)
            shB[half][mp * 4 + i] = (unsigned char)e[i];
        __syncthreads();

        // 256 valid metadata entries (ml % 16 < 8) for 512 m
        int ml = (tid >> 3) * 16 + (tid & 7);
        uint32_t lo = (uint32_t)shB[0][ml]     | ((uint32_t)shB[1][ml] << 8);
        uint32_t hi = (uint32_t)shB[0][ml + 8] | ((uint32_t)shB[1][ml + 8] << 8);
        g_E32[(size_t)cp * M_DIM + mbase + ml] = lo | (hi << 16);
        return;
    }

    // ------- weights + Z: one block per output channel o -------
    int o = bid - 4096;
    int c = tid;
    float b0[8];
    bspline8(0.0f, b0);
    const float* swo = spline_w + ((size_t)(o * CIN + c)) * 32;
    float zt[4];
#pragma unroll
    for (int mn = 0; mn < 4; mn++) {        // raw storage tap (fm, fn)
        float v[8];
        *(float4*)(v)     = *(const float4*)(swo + mn * 8);
        *(float4*)(v + 4) = *(const float4*)(swo + mn * 8 + 4);
        float z = 0.0f;
#pragma unroll
        for (int g = 0; g < 8; g++) z += b0[g] * v[g];
        zt[mn] = z;
        int n = o * 4 + (1 - (mn >> 1)) * 2 + (1 - (mn & 1));
        g_Wb[(size_t)n * K_B + c] =
            __float2half(base_w[((o * CIN + c) * 2 + (mn >> 1)) * 2 + (mn & 1)]);
        __half* dst = g_Wsp + (size_t)n * K_SP + c * 8;
#pragma unroll
        for (int p = 0; p < 8; p++) {
            int g = (p < 4) ? (2 * p) : (2 * (p - 4) + 1);   // even/odd permutation
            dst[p] = __float2half(v[g]);
        }
    }
#pragma unroll
    for (int mn = 0; mn < 4; mn++) red[mn][c] = zt[mn];
    __syncthreads();
    for (int s = 128; s > 0; s >>= 1) {
        if (c < s) {
#pragma unroll
            for (int mn = 0; mn < 4; mn++) red[mn][c] += red[mn][c + s];
        }
        __syncthreads();
    }
    if (c < 4) {
        float total = red[0][0] + red[1][0] + red[2][0] + red[3][0];
        int f = (1 - (c >> 1)) * 2 + (1 - (c & 1));
        g_Z[o * 4 + c] = total - red[f][0];
    }
}

// ---------------- stage loader (3-stage ring) ----------------
__device__ __forceinline__ void issue_loads(int it, int m0, int n0, int tid, uint32_t sb) {
    uint32_t stage = sb + (it % NSTAGE) * STAGE_BYTES;
    if (it < NIT_SP) {
#pragma unroll
        for (int t = 0; t < 6; t++) {
            int idx = tid + t * 256;
            const __half* src;
            uint32_t soff;
            if (idx < 512) {
                int r = idx >> 4, ch = idx & 15;
                src  = g_Fc + (size_t)(it * 32 + r) * M_DIM + m0 + ch * 8;
                soff = stage + r * A_STRIDE + ch * 16;
            } else {
                int i2 = idx - 512;
                int r = i2 >> 3, ch = i2 & 7;
                src  = g_Wsp + (size_t)(n0 + r) * K_SP + it * 64 + ch * 8;
                soff = stage + A_BYTES + r * B_STRIDE + ch * 16;
            }
            cp_async16(soff, src);
        }
    } else {
        int i3 = it - NIT_SP;
#pragma unroll
        for (int t = 0; t < 8; t++) {
            int idx = tid + t * 256;
            const __half* src;
            uint32_t soff;
            if (idx < 1024) {
                int r = idx >> 4, ch = idx & 15;
                src  = g_Fs + (size_t)(i3 * 64 + r) * M_DIM + m0 + ch * 8;
                soff = stage + r * A_STRIDE + ch * 16;
            } else {
                int i2 = idx - 1024;
                int r = i2 >> 3, ch = i2 & 7;
                src  = g_Wb + (size_t)(n0 + r) * K_B + i3 * 64 + ch * 8;
                soff = stage + A_BYTES + r * B_STRIDE + ch * 16;
            }
            cp_async16(soff, src);
        }
    }
}

// ---------------- GEMM: sparse spline + dense silu, fp16, +Z epilogue ----------------
// 3-stage ring, prefetch distance 2 -> ONE barrier per iteration:
// the it+2 write lands in stage (it+2)%3, last read at it-1; the top barrier of
// iteration it guarantees all warps finished it-1's reads.
__global__ void __launch_bounds__(256, 2) k_gemm(float* __restrict__ out) {
    extern __shared__ char smem[];
    uint32_t sb = smem_u32(smem);
    const int tid  = threadIdx.x;
    const int wid  = tid >> 5, lane = tid & 31;
    const int wm   = wid >> 2;           // 0..1 (m: 64 each)
    const int wn   = wid & 3;            // 0..3 (n: 32 each)
    const int m0   = blockIdx.y * 128;
    const int n0   = blockIdx.x * 128;
    const int grp  = lane >> 3, lr = lane & 7;

    const uint32_t a_off = (uint32_t)(((grp >> 1) * 8 + lr) * A_STRIDE +
                                      (grp & 1) * 16 + wm * 128);
    const uint32_t b_off = (uint32_t)(((grp & 1) * 8 + lr) * B_STRIDE +
                                      (grp >> 1) * 16 + wn * 32 * B_STRIDE);

    float acc[4][4][4];
#pragma unroll
    for (int i = 0; i < 4; i++)
#pragma unroll
        for (int j = 0; j < 4; j++)
#pragma unroll
            for (int v = 0; v < 4; v++) acc[i][j][v] = 0.0f;

    issue_loads(0, m0, n0, tid, sb); cp_commit();
    issue_loads(1, m0, n0, tid, sb); cp_commit();

    const int erow = wm * 64 + (lane >> 2);   // frag-relative metadata row
    const int ekh  = lane & 1;                 // metadata k-half
    const uint32_t* __restrict__ ebase =
        g_E32 + (size_t)ekh * M_DIM + m0 + erow;

    for (int it = 0; it < NITER; it++) {
        // metadata LDGs before the pipeline wait: latency overlaps cp.async wait
        uint32_t E[2][4];
        if (it < NIT_SP) {
#pragma unroll
            for (int q = 0; q < 2; q++) {
                size_t cpoff = (size_t)((it * 2 + q) * 2) * M_DIM;
#pragma unroll
                for (int mf = 0; mf < 4; mf++)
                    E[q][mf] = __ldg(ebase + cpoff + mf * 16);
            }
        }

        cp_wait<1>();
        __syncthreads();                       // single barrier per iteration

        // issue next tile immediately (stage (it+2)%3 is free)
        int lt = it + 2;
        if (lt < NITER) issue_loads(lt, m0, n0, tid, sb);
        cp_commit();

        uint32_t st = sb + (it % NSTAGE) * STAGE_BYTES;

        if (it < NIT_SP) {
#pragma unroll
            for (int q = 0; q < 2; q++) {
                uint32_t ac[4][4];
                uint32_t a_base = st + q * (16 * A_STRIDE) + a_off;
#pragma unroll
                for (int mf = 0; mf < 4; mf++)
                    ldsm_x4_t(a_base + mf * 32, ac[mf]);

                uint32_t bb = st + A_BYTES + q * 64 + b_off;
                uint32_t bA[2][4], bB[2][4];
#pragma unroll
                for (int u = 0; u < 2; u++) {
                    ldsm_x4(bb + u * (16 * B_STRIDE), bA[u]);
                    ldsm_x4(bb + 32 + u * (16 * B_STRIDE), bB[u]);
                }
#pragma unroll
                for (int mf = 0; mf < 4; mf++) {
#pragma unroll
                    for (int nf = 0; nf < 4; nf++) {
                        int u = nf >> 1, h = nf & 1;
                        mmasp(acc[mf][nf], ac[mf],
                              bA[u][h], bA[u][h + 2], bB[u][h], bB[u][h + 2],
                              E[q][mf]);
                    }
                }
            }
        } else {
#pragma unroll
            for (int kk = 0; kk < 4; kk++) {
                uint32_t ah[4][4], bh[2][4];
                uint32_t a_base = st + kk * (16 * A_STRIDE) + a_off;
                uint32_t b_base = st + A_BYTES + kk * 32 + b_off;
#pragma unroll
                for (int mf = 0; mf < 4; mf++)
                    ldsm_x4_t(a_base + mf * 32, ah[mf]);
#pragma unroll
                for (int u = 0; u < 2; u++)
                    ldsm_x4(b_base + u * (16 * B_STRIDE), bh[u]);
#pragma unroll
                for (int mf = 0; mf < 4; mf++) {
#pragma unroll
                    for (int nf = 0; nf < 4; nf++) {
                        int u = nf >> 1, h = nf & 1;
                        mma16816(acc[mf][nf], ah[mf], bh[u][h], bh[u][h + 2]);
                    }
                }
            }
        }
    }

    // ---------------- epilogue: add Z, scatter to ConvTranspose layout ----------------
#pragma unroll
    for (int nf = 0; nf < 4; nf++) {
        int n  = n0 + wn * 32 + nf * 8 + (lane & 3) * 2;
        int o  = n >> 2, mi = (n >> 1) & 1;
        float z0 = __ldg(&g_Z[n]), z1 = __ldg(&g_Z[n + 1]);
#pragma unroll
        for (int mf = 0; mf < 4; mf++) {
#pragma unroll
            for (int half = 0; half < 2; half++) {
                int m = m0 + wm * 64 + mf * 16 + (lane >> 2) + half * 8;
                int b = m >> 10, h = (m >> 5) & 31, w = m & 31;
                float2 v;
                v.x = acc[mf][nf][half * 2 + 0] + z0;
                v.y = acc[mf][nf][half * 2 + 1] + z1;
                *(float2*)(out + ((size_t)((b * COUT + o) * 64 + 2 * h + mi)) * 64 + 2 * w) = v;
            }
        }
    }
}

extern "C" void kernel_launch(void* const* d_in, const int* in_sizes, int n_in,
                              void* d_out, int out_size) {
    const float* x        = (const float*)d_in[0];
    const float* base_w   = (const float*)d_in[1];
    const float* spline_w = (const float*)d_in[2];
    float* out = (float*)d_out;

    cudaFuncSetAttribute(k_gemm, cudaFuncAttributeMaxDynamicSharedMemorySize, SMEM_BYTES);

    k_prep<<<4096 + COUT, 256>>>(x, base_w, spline_w);
    dim3 grid(N_DIM / 128, M_DIM / 128);     // (4, 128) = 512 CTAs
    k_gemm<<<grid, 256, SMEM_BYTES>>>(out);
}